// round 14
// baseline (speedup 1.0000x reference)
#include <cuda_runtime.h>
#include <cuda_fp16.h>
#include <math.h>
#include <stdint.h>

// Problem constants
#define DIM   1024
#define NB    64      // n_image == n_caption
#define NS    36      // regions
#define NL    32      // max caption length
#define MROWS (NB*NS)     // 2304 image rows
#define CROWS (NB*NL)     // 2048 caption rows

// ---------------- device scratch (no allocations allowed) ----------------
__device__ float  g_A[MROWS * CROWS];     // attn logits img . E    (2304x2048)
__device__ float  g_C[MROWS * CROWS];     // img . cap dots         (2304x2048)
__device__ float  g_G[NB * NS * NS];      // per-image gram         (64x36x36)
__device__ float  g_w1[CROWS];            // caption word norms     (2048)
__device__ __half g_Ihi[MROWS * DIM], g_Ilo[MROWS * DIM];   // images split
__device__ __half g_Phi[CROWS * DIM], g_Plo[CROWS * DIM];   // captions split
__device__ __half g_Whi[DIM * DIM],   g_Wlo[DIM * DIM];     // W_g split
__device__ __half g_Ehi[CROWS * DIM], g_Elo[CROWS * DIM];   // energy split

__device__ __forceinline__ uint32_t smem_u32(const void* p) {
    uint32_t a;
    asm("{ .reg .u64 t; cvta.to.shared.u64 t, %1; cvt.u32.u64 %0, t; }" : "=r"(a) : "l"(p));
    return a;
}

#define LDSM_X4(r0, r1, r2, r3, addr) \
    asm volatile("ldmatrix.sync.aligned.m8n8.x4.shared.b16 {%0,%1,%2,%3}, [%4];" \
                 : "=r"(r0), "=r"(r1), "=r"(r2), "=r"(r3) : "r"(addr))

#define MMA16816(c0, c1, c2, c3, a0, a1, a2, a3, b0, b1) \
    asm volatile("mma.sync.aligned.m16n8k16.row.col.f32.f16.f16.f32 " \
                 "{%0,%1,%2,%3}, {%4,%5,%6,%7}, {%8,%9}, {%0,%1,%2,%3};" \
                 : "+f"(c0), "+f"(c1), "+f"(c2), "+f"(c3) \
                 : "r"(a0), "r"(a1), "r"(a2), "r"(a3), "r"(b0), "r"(b1))

#define CP_ASYNC16(dst, src) \
    asm volatile("cp.async.cg.shared.global [%0], [%1], 16;" :: "r"(dst), "l"(src))
#define CP_COMMIT() asm volatile("cp.async.commit_group;")
#define CP_WAIT1()  asm volatile("cp.async.wait_group 1;")
#define CP_WAIT0()  asm volatile("cp.async.wait_group 0;")

// =========================================================================
// fp32 -> (hi, lo) fp16 split kernel
// =========================================================================
__global__ __launch_bounds__(256)
void split_kernel(const float4* __restrict__ x, __half2* __restrict__ hi,
                  __half2* __restrict__ lo, int n4) {
    int idx = blockIdx.x * 256 + threadIdx.x;
    if (idx >= n4) return;
    float4 v = x[idx];
    __half2 h0 = __floats2half2_rn(v.x, v.y);
    __half2 h1 = __floats2half2_rn(v.z, v.w);
    float2 f0 = __half22float2(h0);
    float2 f1 = __half22float2(h1);
    hi[2 * idx]     = h0;
    hi[2 * idx + 1] = h1;
    lo[2 * idx]     = __floats2half2_rn(v.x - f0.x, v.y - f0.y);
    lo[2 * idx + 1] = __floats2half2_rn(v.z - f1.x, v.w - f1.y);
}

// =========================================================================
// Split-fp16 tensor-core NT GEMM, cp.async double-buffered, 512 threads.
// D[m][n] = sum_k (Ahi+Alo)[m][k]*(Bhi+Blo)[n][k], dropping lo*lo.
// CTA tile 128x128, 16 warps (4x4), warp tile 32x32, K-chunk 64, 2-stage smem.
// 4 warps/SMSP to hide HMMA latency/banking stalls.
// MODE 0: write fp32 D.  MODE 1: write split fp16 (Dhi, Dlo).
// =========================================================================
#define SROWB 144                  // smem row stride bytes (72 halves)
#define TILE  (128 * SROWB)        // 18432 B per operand tile
#define STAGE (4 * TILE)           // Ah, Al, Bh, Bl
#define GEMM_SMEM (2 * STAGE)      // 147456 B

template<int MODE>
__global__ __launch_bounds__(512, 1)
void gemm_tc_kernel(const __half* __restrict__ Ahi, const __half* __restrict__ Alo,
                    const __half* __restrict__ Bhi, const __half* __restrict__ Blo,
                    float* __restrict__ Df, __half* __restrict__ Dhi, __half* __restrict__ Dlo,
                    int M, int N, int K) {
    extern __shared__ char smem[];
    const uint32_t sbase = smem_u32(smem);

    const int tid = threadIdx.x;
    const int wid = tid >> 5, lane = tid & 31;
    const int rowBase = blockIdx.y * 128;
    const int colBase = blockIdx.x * 128;

    // warp tiling: 4 (m) x 4 (n) warps; warp tile 32x32
    const int mW = (wid >> 2) * 32;
    const int nW = (wid & 3) * 32;

    float acc[2][4][4];
    #pragma unroll
    for (int i = 0; i < 2; i++)
        #pragma unroll
        for (int j = 0; j < 4; j++)
            #pragma unroll
            for (int q = 0; q < 4; q++) acc[i][j][q] = 0.f;

    // ldmatrix source coordinates (fixed per thread)
    const int aRow = mW + (lane & 15);
    const int aColOff = (lane >> 4) * 8;
    const int bRow = nW + (lane & 7) + ((lane >> 4) << 3);
    const int bColOff = ((lane >> 3) & 1) * 8;

    const __half* srcs[4] = {Ahi, Alo, Bhi, Blo};
    const int NC = K >> 6;   // K/64

    // smem stage loader: stage s <- K-chunk c; per array: 2x 16B per thread
    auto load_stage = [&](int s, int c) {
        const uint32_t dstStage = sbase + s * STAGE;
        #pragma unroll
        for (int a = 0; a < 4; a++) {
            const int tileRow = (a < 2) ? rowBase : colBase;
            const __half* src = srcs[a];
            #pragma unroll
            for (int q = 0; q < 2; q++) {
                int id = tid + 512 * q;          // 0..1023
                int row = id >> 3, cc = id & 7;
                const __half* sp = src + (size_t)(tileRow + row) * K + c * 64 + cc * 8;
                uint32_t dp = dstStage + a * TILE + row * SROWB + cc * 16;
                CP_ASYNC16(dp, sp);
            }
        }
        CP_COMMIT();
    };

    load_stage(0, 0);
    if (NC > 1) load_stage(1, 1);

    for (int c = 0; c < NC; c++) {
        if (c + 1 < NC) { CP_WAIT1(); } else { CP_WAIT0(); }
        __syncthreads();

        const uint32_t st = sbase + (c & 1) * STAGE;

        #pragma unroll
        for (int kk = 0; kk < 64; kk += 16) {
            uint32_t Ah[2][4], Al[2][4], Bh[2][4], Bl[2][4];
            #pragma unroll
            for (int i = 0; i < 2; i++) {
                uint32_t ro = (aRow + i * 16) * SROWB + (kk + aColOff) * 2;
                LDSM_X4(Ah[i][0], Ah[i][1], Ah[i][2], Ah[i][3], st + ro);
                LDSM_X4(Al[i][0], Al[i][1], Al[i][2], Al[i][3], st + TILE + ro);
            }
            #pragma unroll
            for (int jp = 0; jp < 2; jp++) {
                uint32_t ro = (bRow + jp * 16) * SROWB + (kk + bColOff) * 2;
                LDSM_X4(Bh[jp][0], Bh[jp][1], Bh[jp][2], Bh[jp][3], st + 2 * TILE + ro);
                LDSM_X4(Bl[jp][0], Bl[jp][1], Bl[jp][2], Bl[jp][3], st + 3 * TILE + ro);
            }
            // Pass 1: hi*hi
            #pragma unroll
            for (int i = 0; i < 2; i++)
                #pragma unroll
                for (int jp = 0; jp < 2; jp++)
                    #pragma unroll
                    for (int h = 0; h < 2; h++) {
                        float* cc2 = acc[i][jp * 2 + h];
                        MMA16816(cc2[0], cc2[1], cc2[2], cc2[3],
                                 Ah[i][0], Ah[i][1], Ah[i][2], Ah[i][3],
                                 Bh[jp][2 * h], Bh[jp][2 * h + 1]);
                    }
            // Pass 2: hi*lo
            #pragma unroll
            for (int i = 0; i < 2; i++)
                #pragma unroll
                for (int jp = 0; jp < 2; jp++)
                    #pragma unroll
                    for (int h = 0; h < 2; h++) {
                        float* cc2 = acc[i][jp * 2 + h];
                        MMA16816(cc2[0], cc2[1], cc2[2], cc2[3],
                                 Ah[i][0], Ah[i][1], Ah[i][2], Ah[i][3],
                                 Bl[jp][2 * h], Bl[jp][2 * h + 1]);
                    }
            // Pass 3: lo*hi
            #pragma unroll
            for (int i = 0; i < 2; i++)
                #pragma unroll
                for (int jp = 0; jp < 2; jp++)
                    #pragma unroll
                    for (int h = 0; h < 2; h++) {
                        float* cc2 = acc[i][jp * 2 + h];
                        MMA16816(cc2[0], cc2[1], cc2[2], cc2[3],
                                 Al[i][0], Al[i][1], Al[i][2], Al[i][3],
                                 Bh[jp][2 * h], Bh[jp][2 * h + 1]);
                    }
        }
        __syncthreads();   // compute done before this buffer is reloaded
        if (c + 2 < NC) load_stage(c & 1, c + 2);
    }

    // ---- epilogue ----
    #pragma unroll
    for (int i = 0; i < 2; i++) {
        const int row0 = rowBase + mW + i * 16 + (lane >> 2);
        #pragma unroll
        for (int j = 0; j < 4; j++) {
            const int col = colBase + nW + j * 8 + (lane & 3) * 2;
            if (MODE == 0) {
                float* d0 = Df + (size_t)row0 * N + col;
                float* d1 = Df + (size_t)(row0 + 8) * N + col;
                d0[0] = acc[i][j][0]; d0[1] = acc[i][j][1];
                d1[0] = acc[i][j][2]; d1[1] = acc[i][j][3];
            } else {
                #pragma unroll
                for (int h = 0; h < 2; h++) {
                    const size_t off = (size_t)(row0 + 8 * h) * N + col;
                    float v0 = acc[i][j][2 * h], v1 = acc[i][j][2 * h + 1];
                    __half2 hv = __floats2half2_rn(v0, v1);
                    float2 hf = __half22float2(hv);
                    __half2 lv = __floats2half2_rn(v0 - hf.x, v1 - hf.y);
                    *(__half2*)(Dhi + off) = hv;
                    *(__half2*)(Dlo + off) = lv;
                }
            }
        }
    }
}

// =========================================================================
// Per-image gram (symmetric): 666 upper-triangle dots per 128-d chunk.
// grid (64, 8), atomicAdd both triangles (G pre-zeroed).
// =========================================================================
__global__ __launch_bounds__(256)
void gram_kernel(const float* __restrict__ img, float* __restrict__ G) {
    __shared__ float ch[NS][132];
    const int b = blockIdx.x;
    const int d0 = blockIdx.y * 128;
    const float* base = img + (size_t)b * NS * DIM + d0;

    for (int idx = threadIdx.x; idx < NS * 32; idx += 256) {
        int s = idx >> 5, c4 = idx & 31;
        *(float4*)&ch[s][c4 * 4] = *(const float4*)(base + (size_t)s * DIM + c4 * 4);
    }
    __syncthreads();

    for (int p = threadIdx.x; p < (NS * (NS + 1)) / 2; p += 256) {
        int idx = p, s = 0, rem = NS;
        while (idx >= rem) { idx -= rem; rem--; s++; }
        int s2 = s + idx;
        const float4* r1 = (const float4*)&ch[s][0];
        const float4* r2 = (const float4*)&ch[s2][0];
        float a = 0.f;
        #pragma unroll
        for (int q = 0; q < 32; q++) {
            float4 x = r1[q], y = r2[q];
            a += x.x * y.x + x.y * y.y + x.z * y.z + x.w * y.w;
        }
        atomicAdd(&G[(size_t)b * NS * NS + s * NS + s2], a);
        if (s2 != s) atomicAdd(&G[(size_t)b * NS * NS + s2 * NS + s], a);
    }
}

// =========================================================================
// Caption word norms
// =========================================================================
__global__ __launch_bounds__(1024)
void capnorm_kernel(const float* __restrict__ cap, float* __restrict__ w1) {
    const int i = blockIdx.x, warp = threadIdx.x >> 5, lane = threadIdx.x & 31;
    const float4* row = (const float4*)(cap + (size_t)(i * NL + warp) * DIM);
    float s = 0.f;
    #pragma unroll 8
    for (int q = lane; q < DIM / 4; q += 32) {
        float4 v = row[q];
        s += v.x * v.x + v.y * v.y + v.z * v.z + v.w * v.w;
    }
    #pragma unroll
    for (int o = 16; o; o >>= 1) s += __shfl_down_sync(0xffffffffu, s, o);
    if (lane == 0) w1[i * NL + warp] = sqrtf(s);
}

// =========================================================================
// Per-(image b, caption i) finishing kernel. grid (i=64, b=64), 128 threads.
// =========================================================================
__global__ __launch_bounds__(128)
void pair_kernel(const float* __restrict__ Aarr, const float* __restrict__ Carr,
                 const float* __restrict__ G, const float* __restrict__ w1,
                 const int* __restrict__ cap_lens, float* __restrict__ out) {
    const int i = blockIdx.x;   // caption
    const int b = blockIdx.y;   // image
    const int tid = threadIdx.x;
    const int len = cap_lens[i];

    __shared__ float T[NS][33];
    __shared__ float Cs[NS][33];
    __shared__ float Gs[NS][37];
    __shared__ float Ws[NL][37];
    __shared__ float ninv[NS];
    __shared__ float w12s[NL], w2s[NL];

    const float* Abase = Aarr + (size_t)(b * NS) * CROWS + i * NL;
    const float* Cbase = Carr + (size_t)(b * NS) * CROWS + i * NL;

    for (int idx = tid; idx < NS * NL; idx += 128) {
        int s = idx >> 5, l = idx & 31;
        float v = Abase[(size_t)s * CROWS + l];
        v = (v > 0.f) ? v : 0.1f * v;       // LeakyReLU(0.1)
        if (l >= len) v = 0.f;              // word mask
        T[s][l]  = v;
        Cs[s][l] = Cbase[(size_t)s * CROWS + l];
    }
    for (int idx = tid; idx < NS * NS; idx += 128)
        Gs[idx / NS][idx % NS] = G[(size_t)b * NS * NS + idx];
    __syncthreads();

    if (tid < NS) {
        float sum = 0.f;
        #pragma unroll
        for (int l = 0; l < NL; l++) { float v = T[tid][l]; sum += v * v; }
        ninv[tid] = 9.0f / (sqrtf(sum) + 1e-8f);
    }
    __syncthreads();

    if (tid < NL) {
        const int l = tid;
        float m = -1e30f;
        #pragma unroll
        for (int s = 0; s < NS; s++) m = fmaxf(m, T[s][l] * ninv[s]);
        float sum = 0.f;
        #pragma unroll
        for (int s = 0; s < NS; s++) {
            float e = __expf(T[s][l] * ninv[s] - m);
            Ws[l][s] = e; sum += e;
        }
        float rr = 1.0f / sum;
        #pragma unroll
        for (int s = 0; s < NS; s++) Ws[l][s] *= rr;
    }
    __syncthreads();

    const int warp = tid >> 5, lane = tid & 31;
    for (int l = warp; l < NL; l += 4) {
        float w12 = 0.f, w2 = 0.f;
        for (int s = lane; s < NS; s += 32) {
            float w = Ws[l][s];
            w12 += w * Cs[s][l];
            float v = 0.f;
            #pragma unroll
            for (int s2 = 0; s2 < NS; s2++) v += Gs[s][s2] * Ws[l][s2];
            w2 += w * v;
        }
        #pragma unroll
        for (int o = 16; o; o >>= 1) {
            w12 += __shfl_down_sync(0xffffffffu, w12, o);
            w2  += __shfl_down_sync(0xffffffffu, w2, o);
        }
        if (lane == 0) { w12s[l] = w12; w2s[l] = w2; }
    }
    __syncthreads();

    if (warp == 0) {
        const int l = lane;
        float z;
        if (l < len) {
            float denom = fmaxf(w1[i * NL + l] * sqrtf(fmaxf(w2s[l], 0.f)), 1e-8f);
            z = 6.0f * (w12s[l] / denom);
        } else {
            z = -1e30f;
        }
        float m = z;
        #pragma unroll
        for (int o = 16; o; o >>= 1) m = fmaxf(m, __shfl_xor_sync(0xffffffffu, m, o));
        float e = expf(z - m);
        #pragma unroll
        for (int o = 16; o; o >>= 1) e += __shfl_xor_sync(0xffffffffu, e, o);
        if (lane == 0) out[b * NB + i] = (m + logf(e)) / 6.0f;
    }
}

// =========================================================================
extern "C" void kernel_launch(void* const* d_in, const int* in_sizes, int n_in,
                              void* d_out, int out_size) {
    const float* images   = (const float*)d_in[0];   // (64,36,1024)
    const float* captions = (const float*)d_in[1];   // (64,32,1024)
    const int*   cap_lens = (const int*)d_in[2];     // (64,)
    const float* W_g      = (const float*)d_in[3];   // (1024,1024)
    float* out = (float*)d_out;                      // (64,64)

    static float *pA = nullptr, *pC = nullptr, *pG = nullptr, *pw1 = nullptr;
    static __half *pIhi, *pIlo, *pPhi, *pPlo, *pWhi, *pWlo, *pEhi, *pElo;
    static bool init = false;
    if (!init) {
        cudaGetSymbolAddress((void**)&pA,  g_A);
        cudaGetSymbolAddress((void**)&pC,  g_C);
        cudaGetSymbolAddress((void**)&pG,  g_G);
        cudaGetSymbolAddress((void**)&pw1, g_w1);
        cudaGetSymbolAddress((void**)&pIhi, g_Ihi);
        cudaGetSymbolAddress((void**)&pIlo, g_Ilo);
        cudaGetSymbolAddress((void**)&pPhi, g_Phi);
        cudaGetSymbolAddress((void**)&pPlo, g_Plo);
        cudaGetSymbolAddress((void**)&pWhi, g_Whi);
        cudaGetSymbolAddress((void**)&pWlo, g_Wlo);
        cudaGetSymbolAddress((void**)&pEhi, g_Ehi);
        cudaGetSymbolAddress((void**)&pElo, g_Elo);
        cudaFuncSetAttribute(gemm_tc_kernel<0>, cudaFuncAttributeMaxDynamicSharedMemorySize, GEMM_SMEM);
        cudaFuncSetAttribute(gemm_tc_kernel<1>, cudaFuncAttributeMaxDynamicSharedMemorySize, GEMM_SMEM);
        init = true;
    }

    // 0) split inputs to fp16 hi/lo
    split_kernel<<<(MROWS * DIM / 4 + 255) / 256, 256>>>((const float4*)images, (__half2*)pIhi, (__half2*)pIlo, MROWS * DIM / 4);
    split_kernel<<<(CROWS * DIM / 4 + 255) / 256, 256>>>((const float4*)captions, (__half2*)pPhi, (__half2*)pPlo, CROWS * DIM / 4);
    split_kernel<<<(DIM * DIM / 4 + 255) / 256, 256>>>((const float4*)W_g, (__half2*)pWhi, (__half2*)pWlo, DIM * DIM / 4);

    // 1) E = captions @ W_g^T  -> split fp16 output (2048 x 1024)
    gemm_tc_kernel<1><<<dim3(DIM / 128, CROWS / 128), 512, GEMM_SMEM>>>(
        pPhi, pPlo, pWhi, pWlo, nullptr, pEhi, pElo, CROWS, DIM, DIM);
    // 2) A = images @ E^T       (2304 x 2048) fp32
    gemm_tc_kernel<0><<<dim3(CROWS / 128, MROWS / 128), 512, GEMM_SMEM>>>(
        pIhi, pIlo, pEhi, pElo, pA, nullptr, nullptr, MROWS, CROWS, DIM);
    // 3) C = images @ captions^T (2304 x 2048) fp32
    gemm_tc_kernel<0><<<dim3(CROWS / 128, MROWS / 128), 512, GEMM_SMEM>>>(
        pIhi, pIlo, pPhi, pPlo, pC, nullptr, nullptr, MROWS, CROWS, DIM);
    // 4) per-image grams (zero then atomic-accumulate over 8 D-chunks)
    cudaMemsetAsync(pG, 0, (size_t)NB * NS * NS * sizeof(float));
    gram_kernel<<<dim3(NB, 8), 256>>>(images, pG);
    // 5) caption word norms
    capnorm_kernel<<<NB, 1024>>>(captions, pw1);
    // 6) per-pair finishing
    pair_kernel<<<dim3(NB, NB), 128>>>(pA, pC, pG, pw1, cap_lens, out);
}

// round 15
// speedup vs baseline: 1.0478x; 1.0478x over previous
#include <cuda_runtime.h>
#include <cuda_fp16.h>
#include <math.h>
#include <stdint.h>

// Problem constants
#define DIM   1024
#define NB    64      // n_image == n_caption
#define NS    36      // regions
#define NL    32      // max caption length
#define MROWS (NB*NS)     // 2304 image rows
#define CROWS (NB*NL)     // 2048 caption rows

// ---------------- device scratch (no allocations allowed) ----------------
__device__ float  g_A[MROWS * CROWS];     // attn logits img . E    (2304x2048)
__device__ float  g_C[MROWS * CROWS];     // img . cap dots         (2304x2048)
__device__ float  g_G[NB * NS * NS];      // per-image gram         (64x36x36)
__device__ float  g_w1[CROWS];            // caption word norms     (2048)
__device__ __half g_Ihi[MROWS * DIM], g_Ilo[MROWS * DIM];   // images split
__device__ __half g_Phi[CROWS * DIM], g_Plo[CROWS * DIM];   // captions split
__device__ __half g_Whi[DIM * DIM],   g_Wlo[DIM * DIM];     // W_g split
__device__ __half g_Ehi[CROWS * DIM], g_Elo[CROWS * DIM];   // energy split

__device__ __forceinline__ uint32_t smem_u32(const void* p) {
    uint32_t a;
    asm("{ .reg .u64 t; cvta.to.shared.u64 t, %1; cvt.u32.u64 %0, t; }" : "=r"(a) : "l"(p));
    return a;
}

#define LDSM_X4(r0, r1, r2, r3, addr) \
    asm volatile("ldmatrix.sync.aligned.m8n8.x4.shared.b16 {%0,%1,%2,%3}, [%4];" \
                 : "=r"(r0), "=r"(r1), "=r"(r2), "=r"(r3) : "r"(addr))

// fp32-accumulator MMA (half-rate) — used for the dominant hi*hi product
#define MMA16816(c0, c1, c2, c3, a0, a1, a2, a3, b0, b1) \
    asm volatile("mma.sync.aligned.m16n8k16.row.col.f32.f16.f16.f32 " \
                 "{%0,%1,%2,%3}, {%4,%5,%6,%7}, {%8,%9}, {%0,%1,%2,%3};" \
                 : "+f"(c0), "+f"(c1), "+f"(c2), "+f"(c3) \
                 : "r"(a0), "r"(a1), "r"(a2), "r"(a3), "r"(b0), "r"(b1))

// fp16-accumulator MMA (full-rate) — used for the small hl/lh corrections
#define MMA16816H(c0, c1, a0, a1, a2, a3, b0, b1) \
    asm volatile("mma.sync.aligned.m16n8k16.row.col.f16.f16.f16.f16 " \
                 "{%0,%1}, {%2,%3,%4,%5}, {%6,%7}, {%0,%1};" \
                 : "+r"(c0), "+r"(c1) \
                 : "r"(a0), "r"(a1), "r"(a2), "r"(a3), "r"(b0), "r"(b1))

#define CP_ASYNC16(dst, src) \
    asm volatile("cp.async.cg.shared.global [%0], [%1], 16;" :: "r"(dst), "l"(src))
#define CP_COMMIT() asm volatile("cp.async.commit_group;")
#define CP_WAIT1()  asm volatile("cp.async.wait_group 1;")
#define CP_WAIT0()  asm volatile("cp.async.wait_group 0;")

// =========================================================================
// fp32 -> (hi, lo) fp16 split kernel
// =========================================================================
__global__ __launch_bounds__(256)
void split_kernel(const float4* __restrict__ x, __half2* __restrict__ hi,
                  __half2* __restrict__ lo, int n4) {
    int idx = blockIdx.x * 256 + threadIdx.x;
    if (idx >= n4) return;
    float4 v = x[idx];
    __half2 h0 = __floats2half2_rn(v.x, v.y);
    __half2 h1 = __floats2half2_rn(v.z, v.w);
    float2 f0 = __half22float2(h0);
    float2 f1 = __half22float2(h1);
    hi[2 * idx]     = h0;
    hi[2 * idx + 1] = h1;
    lo[2 * idx]     = __floats2half2_rn(v.x - f0.x, v.y - f0.y);
    lo[2 * idx + 1] = __floats2half2_rn(v.z - f1.x, v.w - f1.y);
}

// =========================================================================
// Split-fp16 tensor-core NT GEMM, cp.async double-buffered.
// D = Ahi*Bhi (fp32 accum, half-rate) + [Ahi*Blo + Alo*Bhi] (fp16 accum,
// full-rate, shared accumulator), dropping lo*lo (~2^-22).
// CTA tile 128x128, 8 warps, warp tile 64x32, K-chunk 64, 2-stage smem.
// MODE 0: write fp32 D.  MODE 1: write split fp16 (Dhi, Dlo).
// =========================================================================
#define SROWB 144                  // smem row stride bytes (72 halves)
#define TILE  (128 * SROWB)        // 18432 B per operand tile
#define STAGE (4 * TILE)           // Ah, Al, Bh, Bl
#define GEMM_SMEM (2 * STAGE)      // 147456 B

template<int MODE>
__global__ __launch_bounds__(256, 1)
void gemm_tc_kernel(const __half* __restrict__ Ahi, const __half* __restrict__ Alo,
                    const __half* __restrict__ Bhi, const __half* __restrict__ Blo,
                    float* __restrict__ Df, __half* __restrict__ Dhi, __half* __restrict__ Dlo,
                    int M, int N, int K) {
    extern __shared__ char smem[];
    const uint32_t sbase = smem_u32(smem);

    const int tid = threadIdx.x;
    const int wid = tid >> 5, lane = tid & 31;
    const int rowBase = blockIdx.y * 128;
    const int colBase = blockIdx.x * 128;

    // warp tiling: 2 (m) x 4 (n) warps; warp tile 64x32
    const int mW = (wid >> 2) * 64;
    const int nW = (wid & 3) * 32;

    float acc[4][4][4];          // hi*hi, fp32
    uint32_t accH[4][4][2];      // hl + lh corrections, fp16x2 packed
    #pragma unroll
    for (int i = 0; i < 4; i++)
        #pragma unroll
        for (int j = 0; j < 4; j++) {
            #pragma unroll
            for (int q = 0; q < 4; q++) acc[i][j][q] = 0.f;
            accH[i][j][0] = 0u; accH[i][j][1] = 0u;
        }

    // ldmatrix source coordinates (fixed per thread)
    const int aRow = mW + (lane & 15);
    const int aColOff = (lane >> 4) * 8;
    const int bRow = nW + (lane & 7) + ((lane >> 4) << 3);
    const int bColOff = ((lane >> 3) & 1) * 8;

    const __half* srcs[4] = {Ahi, Alo, Bhi, Blo};
    const int NC = K >> 6;   // K/64

    // loader: stage s <- K-chunk c; per array: 4x 16B per thread
    auto load_stage = [&](int s, int c) {
        const uint32_t dstStage = sbase + s * STAGE;
        #pragma unroll
        for (int a = 0; a < 4; a++) {
            const int tileRow = (a < 2) ? rowBase : colBase;
            const __half* src = srcs[a];
            #pragma unroll
            for (int q = 0; q < 4; q++) {
                int id = tid + 256 * q;          // 0..1023
                int row = id >> 3, cc = id & 7;
                const __half* sp = src + (size_t)(tileRow + row) * K + c * 64 + cc * 8;
                uint32_t dp = dstStage + a * TILE + row * SROWB + cc * 16;
                CP_ASYNC16(dp, sp);
            }
        }
        CP_COMMIT();
    };

    load_stage(0, 0);
    if (NC > 1) load_stage(1, 1);

    for (int c = 0; c < NC; c++) {
        if (c + 1 < NC) { CP_WAIT1(); } else { CP_WAIT0(); }
        __syncthreads();

        const uint32_t st = sbase + (c & 1) * STAGE;

        #pragma unroll
        for (int kk = 0; kk < 64; kk += 16) {
            uint32_t Ah[4][4], Al[4][4], Bh[2][4], Bl[2][4];
            #pragma unroll
            for (int i = 0; i < 4; i++) {
                uint32_t ro = (aRow + i * 16) * SROWB + (kk + aColOff) * 2;
                LDSM_X4(Ah[i][0], Ah[i][1], Ah[i][2], Ah[i][3], st + ro);
                LDSM_X4(Al[i][0], Al[i][1], Al[i][2], Al[i][3], st + TILE + ro);
            }
            #pragma unroll
            for (int jp = 0; jp < 2; jp++) {
                uint32_t ro = (bRow + jp * 16) * SROWB + (kk + bColOff) * 2;
                LDSM_X4(Bh[jp][0], Bh[jp][1], Bh[jp][2], Bh[jp][3], st + 2 * TILE + ro);
                LDSM_X4(Bl[jp][0], Bl[jp][1], Bl[jp][2], Bl[jp][3], st + 3 * TILE + ro);
            }
            // Pass 1: hi*hi (fp32 accum, half-rate)
            #pragma unroll
            for (int i = 0; i < 4; i++)
                #pragma unroll
                for (int jp = 0; jp < 2; jp++)
                    #pragma unroll
                    for (int h = 0; h < 2; h++) {
                        float* cc2 = acc[i][jp * 2 + h];
                        MMA16816(cc2[0], cc2[1], cc2[2], cc2[3],
                                 Ah[i][0], Ah[i][1], Ah[i][2], Ah[i][3],
                                 Bh[jp][2 * h], Bh[jp][2 * h + 1]);
                    }
            // Pass 2: hi*lo (fp16 accum, full-rate)
            #pragma unroll
            for (int i = 0; i < 4; i++)
                #pragma unroll
                for (int jp = 0; jp < 2; jp++)
                    #pragma unroll
                    for (int h = 0; h < 2; h++) {
                        uint32_t* cH = accH[i][jp * 2 + h];
                        MMA16816H(cH[0], cH[1],
                                  Ah[i][0], Ah[i][1], Ah[i][2], Ah[i][3],
                                  Bl[jp][2 * h], Bl[jp][2 * h + 1]);
                    }
            // Pass 3: lo*hi (fp16 accum, full-rate, same accumulator)
            #pragma unroll
            for (int i = 0; i < 4; i++)
                #pragma unroll
                for (int jp = 0; jp < 2; jp++)
                    #pragma unroll
                    for (int h = 0; h < 2; h++) {
                        uint32_t* cH = accH[i][jp * 2 + h];
                        MMA16816H(cH[0], cH[1],
                                  Al[i][0], Al[i][1], Al[i][2], Al[i][3],
                                  Bh[jp][2 * h], Bh[jp][2 * h + 1]);
                    }
        }
        __syncthreads();   // compute done before this buffer is reloaded
        if (c + 2 < NC) load_stage(c & 1, c + 2);
    }

    // ---- epilogue: D = acc(f32) + unpack(accH f16) ----
    #pragma unroll
    for (int i = 0; i < 4; i++) {
        const int row0 = rowBase + mW + i * 16 + (lane >> 2);
        #pragma unroll
        for (int j = 0; j < 4; j++) {
            const int col = colBase + nW + j * 8 + (lane & 3) * 2;
            float2 c0 = __half22float2(*(__half2*)&accH[i][j][0]);  // row0, cols (0,1)
            float2 c1 = __half22float2(*(__half2*)&accH[i][j][1]);  // row0+8, cols (0,1)
            float v00 = acc[i][j][0] + c0.x;
            float v01 = acc[i][j][1] + c0.y;
            float v10 = acc[i][j][2] + c1.x;
            float v11 = acc[i][j][3] + c1.y;
            if (MODE == 0) {
                float* d0 = Df + (size_t)row0 * N + col;
                float* d1 = Df + (size_t)(row0 + 8) * N + col;
                d0[0] = v00; d0[1] = v01;
                d1[0] = v10; d1[1] = v11;
            } else {
                float vs[2][2] = {{v00, v01}, {v10, v11}};
                #pragma unroll
                for (int h = 0; h < 2; h++) {
                    const size_t off = (size_t)(row0 + 8 * h) * N + col;
                    __half2 hv = __floats2half2_rn(vs[h][0], vs[h][1]);
                    float2 hf = __half22float2(hv);
                    __half2 lv = __floats2half2_rn(vs[h][0] - hf.x, vs[h][1] - hf.y);
                    *(__half2*)(Dhi + off) = hv;
                    *(__half2*)(Dlo + off) = lv;
                }
            }
        }
    }
}

// =========================================================================
// Per-image gram (symmetric): 666 upper-triangle dots per 128-d chunk.
// grid (64, 8), atomicAdd both triangles (G pre-zeroed).
// =========================================================================
__global__ __launch_bounds__(256)
void gram_kernel(const float* __restrict__ img, float* __restrict__ G) {
    __shared__ float ch[NS][132];
    const int b = blockIdx.x;
    const int d0 = blockIdx.y * 128;
    const float* base = img + (size_t)b * NS * DIM + d0;

    for (int idx = threadIdx.x; idx < NS * 32; idx += 256) {
        int s = idx >> 5, c4 = idx & 31;
        *(float4*)&ch[s][c4 * 4] = *(const float4*)(base + (size_t)s * DIM + c4 * 4);
    }
    __syncthreads();

    for (int p = threadIdx.x; p < (NS * (NS + 1)) / 2; p += 256) {
        int idx = p, s = 0, rem = NS;
        while (idx >= rem) { idx -= rem; rem--; s++; }
        int s2 = s + idx;
        const float4* r1 = (const float4*)&ch[s][0];
        const float4* r2 = (const float4*)&ch[s2][0];
        float a = 0.f;
        #pragma unroll
        for (int q = 0; q < 32; q++) {
            float4 x = r1[q], y = r2[q];
            a += x.x * y.x + x.y * y.y + x.z * y.z + x.w * y.w;
        }
        atomicAdd(&G[(size_t)b * NS * NS + s * NS + s2], a);
        if (s2 != s) atomicAdd(&G[(size_t)b * NS * NS + s2 * NS + s], a);
    }
}

// =========================================================================
// Caption word norms
// =========================================================================
__global__ __launch_bounds__(1024)
void capnorm_kernel(const float* __restrict__ cap, float* __restrict__ w1) {
    const int i = blockIdx.x, warp = threadIdx.x >> 5, lane = threadIdx.x & 31;
    const float4* row = (const float4*)(cap + (size_t)(i * NL + warp) * DIM);
    float s = 0.f;
    #pragma unroll 8
    for (int q = lane; q < DIM / 4; q += 32) {
        float4 v = row[q];
        s += v.x * v.x + v.y * v.y + v.z * v.z + v.w * v.w;
    }
    #pragma unroll
    for (int o = 16; o; o >>= 1) s += __shfl_down_sync(0xffffffffu, s, o);
    if (lane == 0) w1[i * NL + warp] = sqrtf(s);
}

// =========================================================================
// Per-(image b, caption i) finishing kernel. grid (i=64, b=64), 128 threads.
// =========================================================================
__global__ __launch_bounds__(128)
void pair_kernel(const float* __restrict__ Aarr, const float* __restrict__ Carr,
                 const float* __restrict__ G, const float* __restrict__ w1,
                 const int* __restrict__ cap_lens, float* __restrict__ out) {
    const int i = blockIdx.x;   // caption
    const int b = blockIdx.y;   // image
    const int tid = threadIdx.x;
    const int len = cap_lens[i];

    __shared__ float T[NS][33];
    __shared__ float Cs[NS][33];
    __shared__ float Gs[NS][37];
    __shared__ float Ws[NL][37];
    __shared__ float ninv[NS];
    __shared__ float w12s[NL], w2s[NL];

    const float* Abase = Aarr + (size_t)(b * NS) * CROWS + i * NL;
    const float* Cbase = Carr + (size_t)(b * NS) * CROWS + i * NL;

    for (int idx = tid; idx < NS * NL; idx += 128) {
        int s = idx >> 5, l = idx & 31;
        float v = Abase[(size_t)s * CROWS + l];
        v = (v > 0.f) ? v : 0.1f * v;       // LeakyReLU(0.1)
        if (l >= len) v = 0.f;              // word mask
        T[s][l]  = v;
        Cs[s][l] = Cbase[(size_t)s * CROWS + l];
    }
    for (int idx = tid; idx < NS * NS; idx += 128)
        Gs[idx / NS][idx % NS] = G[(size_t)b * NS * NS + idx];
    __syncthreads();

    if (tid < NS) {
        float sum = 0.f;
        #pragma unroll
        for (int l = 0; l < NL; l++) { float v = T[tid][l]; sum += v * v; }
        ninv[tid] = 9.0f / (sqrtf(sum) + 1e-8f);
    }
    __syncthreads();

    if (tid < NL) {
        const int l = tid;
        float m = -1e30f;
        #pragma unroll
        for (int s = 0; s < NS; s++) m = fmaxf(m, T[s][l] * ninv[s]);
        float sum = 0.f;
        #pragma unroll
        for (int s = 0; s < NS; s++) {
            float e = __expf(T[s][l] * ninv[s] - m);
            Ws[l][s] = e; sum += e;
        }
        float rr = 1.0f / sum;
        #pragma unroll
        for (int s = 0; s < NS; s++) Ws[l][s] *= rr;
    }
    __syncthreads();

    const int warp = tid >> 5, lane = tid & 31;
    for (int l = warp; l < NL; l += 4) {
        float w12 = 0.f, w2 = 0.f;
        for (int s = lane; s < NS; s += 32) {
            float w = Ws[l][s];
            w12 += w * Cs[s][l];
            float v = 0.f;
            #pragma unroll
            for (int s2 = 0; s2 < NS; s2++) v += Gs[s][s2] * Ws[l][s2];
            w2 += w * v;
        }
        #pragma unroll
        for (int o = 16; o; o >>= 1) {
            w12 += __shfl_down_sync(0xffffffffu, w12, o);
            w2  += __shfl_down_sync(0xffffffffu, w2, o);
        }
        if (lane == 0) { w12s[l] = w12; w2s[l] = w2; }
    }
    __syncthreads();

    if (warp == 0) {
        const int l = lane;
        float z;
        if (l < len) {
            float denom = fmaxf(w1[i * NL + l] * sqrtf(fmaxf(w2s[l], 0.f)), 1e-8f);
            z = 6.0f * (w12s[l] / denom);
        } else {
            z = -1e30f;
        }
        float m = z;
        #pragma unroll
        for (int o = 16; o; o >>= 1) m = fmaxf(m, __shfl_xor_sync(0xffffffffu, m, o));
        float e = expf(z - m);
        #pragma unroll
        for (int o = 16; o; o >>= 1) e += __shfl_xor_sync(0xffffffffu, e, o);
        if (lane == 0) out[b * NB + i] = (m + logf(e)) / 6.0f;
    }
}

// =========================================================================
extern "C" void kernel_launch(void* const* d_in, const int* in_sizes, int n_in,
                              void* d_out, int out_size) {
    const float* images   = (const float*)d_in[0];   // (64,36,1024)
    const float* captions = (const float*)d_in[1];   // (64,32,1024)
    const int*   cap_lens = (const int*)d_in[2];     // (64,)
    const float* W_g      = (const float*)d_in[3];   // (1024,1024)
    float* out = (float*)d_out;                      // (64,64)

    static float *pA = nullptr, *pC = nullptr, *pG = nullptr, *pw1 = nullptr;
    static __half *pIhi, *pIlo, *pPhi, *pPlo, *pWhi, *pWlo, *pEhi, *pElo;
    static bool init = false;
    if (!init) {
        cudaGetSymbolAddress((void**)&pA,  g_A);
        cudaGetSymbolAddress((void**)&pC,  g_C);
        cudaGetSymbolAddress((void**)&pG,  g_G);
        cudaGetSymbolAddress((void**)&pw1, g_w1);
        cudaGetSymbolAddress((void**)&pIhi, g_Ihi);
        cudaGetSymbolAddress((void**)&pIlo, g_Ilo);
        cudaGetSymbolAddress((void**)&pPhi, g_Phi);
        cudaGetSymbolAddress((void**)&pPlo, g_Plo);
        cudaGetSymbolAddress((void**)&pWhi, g_Whi);
        cudaGetSymbolAddress((void**)&pWlo, g_Wlo);
        cudaGetSymbolAddress((void**)&pEhi, g_Ehi);
        cudaGetSymbolAddress((void**)&pElo, g_Elo);
        cudaFuncSetAttribute(gemm_tc_kernel<0>, cudaFuncAttributeMaxDynamicSharedMemorySize, GEMM_SMEM);
        cudaFuncSetAttribute(gemm_tc_kernel<1>, cudaFuncAttributeMaxDynamicSharedMemorySize, GEMM_SMEM);
        init = true;
    }

    // 0) split inputs to fp16 hi/lo
    split_kernel<<<(MROWS * DIM / 4 + 255) / 256, 256>>>((const float4*)images, (__half2*)pIhi, (__half2*)pIlo, MROWS * DIM / 4);
    split_kernel<<<(CROWS * DIM / 4 + 255) / 256, 256>>>((const float4*)captions, (__half2*)pPhi, (__half2*)pPlo, CROWS * DIM / 4);
    split_kernel<<<(DIM * DIM / 4 + 255) / 256, 256>>>((const float4*)W_g, (__half2*)pWhi, (__half2*)pWlo, DIM * DIM / 4);

    // 1) E = captions @ W_g^T  -> split fp16 output (2048 x 1024)
    gemm_tc_kernel<1><<<dim3(DIM / 128, CROWS / 128), 256, GEMM_SMEM>>>(
        pPhi, pPlo, pWhi, pWlo, nullptr, pEhi, pElo, CROWS, DIM, DIM);
    // 2) A = images @ E^T       (2304 x 2048) fp32
    gemm_tc_kernel<0><<<dim3(CROWS / 128, MROWS / 128), 256, GEMM_SMEM>>>(
        pIhi, pIlo, pEhi, pElo, pA, nullptr, nullptr, MROWS, CROWS, DIM);
    // 3) C = images @ captions^T (2304 x 2048) fp32
    gemm_tc_kernel<0><<<dim3(CROWS / 128, MROWS / 128), 256, GEMM_SMEM>>>(
        pIhi, pIlo, pPhi, pPlo, pC, nullptr, nullptr, MROWS, CROWS, DIM);
    // 4) per-image grams (zero then atomic-accumulate over 8 D-chunks)
    cudaMemsetAsync(pG, 0, (size_t)NB * NS * NS * sizeof(float));
    gram_kernel<<<dim3(NB, 8), 256>>>(images, pG);
    // 5) caption word norms
    capnorm_kernel<<<NB, 1024>>>(captions, pw1);
    // 6) per-pair finishing
    pair_kernel<<<dim3(NB, NB), 128>>>(pA, pC, pG, pw1, cap_lens, out);
}

// round 16
// speedup vs baseline: 1.1685x; 1.1152x over previous
#include <cuda_runtime.h>
#include <cuda_fp16.h>
#include <math.h>
#include <stdint.h>

// Problem constants
#define DIM   1024
#define NB    64      // n_image == n_caption
#define NS    36      // regions
#define NL    32      // max caption length
#define MROWS (NB*NS)     // 2304 image rows
#define CROWS (NB*NL)     // 2048 caption rows

// ---------------- device scratch (no allocations allowed) ----------------
__device__ float  g_A[MROWS * CROWS];     // attn logits img . E    (2304x2048)
__device__ float  g_C[MROWS * CROWS];     // img . cap dots         (2304x2048)
__device__ float  g_G[NB * NS * NS];      // per-image gram         (64x36x36)
__device__ float  g_w1[CROWS];            // caption word norms     (2048)
__device__ __half g_Ihi[MROWS * DIM], g_Ilo[MROWS * DIM];   // images split
__device__ __half g_Phi[CROWS * DIM], g_Plo[CROWS * DIM];   // captions split
__device__ __half g_Whi[DIM * DIM],   g_Wlo[DIM * DIM];     // W_g split
__device__ __half g_Ehi[CROWS * DIM], g_Elo[CROWS * DIM];   // energy split

__device__ __forceinline__ uint32_t smem_u32(const void* p) {
    uint32_t a;
    asm("{ .reg .u64 t; cvta.to.shared.u64 t, %1; cvt.u32.u64 %0, t; }" : "=r"(a) : "l"(p));
    return a;
}

#define LDSM_X4(r0, r1, r2, r3, addr) \
    asm volatile("ldmatrix.sync.aligned.m8n8.x4.shared.b16 {%0,%1,%2,%3}, [%4];" \
                 : "=r"(r0), "=r"(r1), "=r"(r2), "=r"(r3) : "r"(addr))

// fp32-accumulator MMA — dominant hi*hi product
#define MMA16816(c0, c1, c2, c3, a0, a1, a2, a3, b0, b1) \
    asm volatile("mma.sync.aligned.m16n8k16.row.col.f32.f16.f16.f32 " \
                 "{%0,%1,%2,%3}, {%4,%5,%6,%7}, {%8,%9}, {%0,%1,%2,%3};" \
                 : "+f"(c0), "+f"(c1), "+f"(c2), "+f"(c3) \
                 : "r"(a0), "r"(a1), "r"(a2), "r"(a3), "r"(b0), "r"(b1))

// fp16-accumulator MMA — small hl/lh corrections
#define MMA16816H(c0, c1, a0, a1, a2, a3, b0, b1) \
    asm volatile("mma.sync.aligned.m16n8k16.row.col.f16.f16.f16.f16 " \
                 "{%0,%1}, {%2,%3,%4,%5}, {%6,%7}, {%0,%1};" \
                 : "+r"(c0), "+r"(c1) \
                 : "r"(a0), "r"(a1), "r"(a2), "r"(a3), "r"(b0), "r"(b1))

#define CP_ASYNC16(dst, src) \
    asm volatile("cp.async.cg.shared.global [%0], [%1], 16;" :: "r"(dst), "l"(src))
#define CP_COMMIT() asm volatile("cp.async.commit_group;")
#define CP_WAIT1()  asm volatile("cp.async.wait_group 1;")
#define CP_WAIT0()  asm volatile("cp.async.wait_group 0;")

// =========================================================================
// fp32 -> (hi, lo) fp16 split kernel
// =========================================================================
__global__ __launch_bounds__(256)
void split_kernel(const float4* __restrict__ x, __half2* __restrict__ hi,
                  __half2* __restrict__ lo, int n4) {
    int idx = blockIdx.x * 256 + threadIdx.x;
    if (idx >= n4) return;
    float4 v = x[idx];
    __half2 h0 = __floats2half2_rn(v.x, v.y);
    __half2 h1 = __floats2half2_rn(v.z, v.w);
    float2 f0 = __half22float2(h0);
    float2 f1 = __half22float2(h1);
    hi[2 * idx]     = h0;
    hi[2 * idx + 1] = h1;
    lo[2 * idx]     = __floats2half2_rn(v.x - f0.x, v.y - f0.y);
    lo[2 * idx + 1] = __floats2half2_rn(v.z - f1.x, v.w - f1.y);
}

// =========================================================================
// Split-fp16 tensor-core NT GEMM, cp.async double-buffered.
// NPROD=3: D = Ahi*Bhi (f32 acc) + [Ahi*Blo + Alo*Bhi] (f16 acc)
// NPROD=2: D = Ahi*Bhi (f32 acc) + [Ahi*Blo] (f16 acc)   (drop lo*hi, ~2.4e-4)
// CTA tile 128x128, 8 warps, warp tile 64x32, K-chunk 64, 2-stage smem.
// MODE 0: write fp32 D.  MODE 1: write split fp16 (Dhi, Dlo).
// =========================================================================
#define SROWB 144                  // smem row stride bytes (72 halves)
#define TILE  (128 * SROWB)        // 18432 B per operand tile
#define STAGE (4 * TILE)           // Ah, Al, Bh, Bl
#define GEMM_SMEM (2 * STAGE)      // 147456 B

template<int MODE, int NPROD>
__global__ __launch_bounds__(256, 1)
void gemm_tc_kernel(const __half* __restrict__ Ahi, const __half* __restrict__ Alo,
                    const __half* __restrict__ Bhi, const __half* __restrict__ Blo,
                    float* __restrict__ Df, __half* __restrict__ Dhi, __half* __restrict__ Dlo,
                    int M, int N, int K) {
    extern __shared__ char smem[];
    const uint32_t sbase = smem_u32(smem);

    const int tid = threadIdx.x;
    const int wid = tid >> 5, lane = tid & 31;
    const int rowBase = blockIdx.y * 128;
    const int colBase = blockIdx.x * 128;

    // warp tiling: 2 (m) x 4 (n) warps; warp tile 64x32
    const int mW = (wid >> 2) * 64;
    const int nW = (wid & 3) * 32;

    float acc[4][4][4];          // hi*hi, fp32
    uint32_t accH[4][4][2];      // corrections, fp16x2 packed
    #pragma unroll
    for (int i = 0; i < 4; i++)
        #pragma unroll
        for (int j = 0; j < 4; j++) {
            #pragma unroll
            for (int q = 0; q < 4; q++) acc[i][j][q] = 0.f;
            accH[i][j][0] = 0u; accH[i][j][1] = 0u;
        }

    // ldmatrix source coordinates (fixed per thread)
    const int aRow = mW + (lane & 15);
    const int aColOff = (lane >> 4) * 8;
    const int bRow = nW + (lane & 7) + ((lane >> 4) << 3);
    const int bColOff = ((lane >> 3) & 1) * 8;

    const __half* srcs[4] = {Ahi, Alo, Bhi, Blo};
    const int NC = K >> 6;   // K/64

    // loader: stage s <- K-chunk c; per array: 4x 16B per thread
    auto load_stage = [&](int s, int c) {
        const uint32_t dstStage = sbase + s * STAGE;
        #pragma unroll
        for (int a = 0; a < 4; a++) {
            const int tileRow = (a < 2) ? rowBase : colBase;
            const __half* src = srcs[a];
            #pragma unroll
            for (int q = 0; q < 4; q++) {
                int id = tid + 256 * q;          // 0..1023
                int row = id >> 3, cc = id & 7;
                const __half* sp = src + (size_t)(tileRow + row) * K + c * 64 + cc * 8;
                uint32_t dp = dstStage + a * TILE + row * SROWB + cc * 16;
                CP_ASYNC16(dp, sp);
            }
        }
        CP_COMMIT();
    };

    load_stage(0, 0);
    if (NC > 1) load_stage(1, 1);

    for (int c = 0; c < NC; c++) {
        if (c + 1 < NC) { CP_WAIT1(); } else { CP_WAIT0(); }
        __syncthreads();

        const uint32_t st = sbase + (c & 1) * STAGE;

        #pragma unroll
        for (int kk = 0; kk < 64; kk += 16) {
            uint32_t Ah[4][4], Al[4][4], Bh[2][4], Bl[2][4];
            #pragma unroll
            for (int i = 0; i < 4; i++) {
                uint32_t ro = (aRow + i * 16) * SROWB + (kk + aColOff) * 2;
                LDSM_X4(Ah[i][0], Ah[i][1], Ah[i][2], Ah[i][3], st + ro);
                if (NPROD == 3) {
                    LDSM_X4(Al[i][0], Al[i][1], Al[i][2], Al[i][3], st + TILE + ro);
                }
            }
            #pragma unroll
            for (int jp = 0; jp < 2; jp++) {
                uint32_t ro = (bRow + jp * 16) * SROWB + (kk + bColOff) * 2;
                LDSM_X4(Bh[jp][0], Bh[jp][1], Bh[jp][2], Bh[jp][3], st + 2 * TILE + ro);
                LDSM_X4(Bl[jp][0], Bl[jp][1], Bl[jp][2], Bl[jp][3], st + 3 * TILE + ro);
            }
            // Pass 1: hi*hi (fp32 accum)
            #pragma unroll
            for (int i = 0; i < 4; i++)
                #pragma unroll
                for (int jp = 0; jp < 2; jp++)
                    #pragma unroll
                    for (int h = 0; h < 2; h++) {
                        float* cc2 = acc[i][jp * 2 + h];
                        MMA16816(cc2[0], cc2[1], cc2[2], cc2[3],
                                 Ah[i][0], Ah[i][1], Ah[i][2], Ah[i][3],
                                 Bh[jp][2 * h], Bh[jp][2 * h + 1]);
                    }
            // Pass 2: hi*lo (fp16 accum)
            #pragma unroll
            for (int i = 0; i < 4; i++)
                #pragma unroll
                for (int jp = 0; jp < 2; jp++)
                    #pragma unroll
                    for (int h = 0; h < 2; h++) {
                        uint32_t* cH = accH[i][jp * 2 + h];
                        MMA16816H(cH[0], cH[1],
                                  Ah[i][0], Ah[i][1], Ah[i][2], Ah[i][3],
                                  Bl[jp][2 * h], Bl[jp][2 * h + 1]);
                    }
            // Pass 3: lo*hi (fp16 accum, same accumulator) — NPROD==3 only
            if (NPROD == 3) {
                #pragma unroll
                for (int i = 0; i < 4; i++)
                    #pragma unroll
                    for (int jp = 0; jp < 2; jp++)
                        #pragma unroll
                        for (int h = 0; h < 2; h++) {
                            uint32_t* cH = accH[i][jp * 2 + h];
                            MMA16816H(cH[0], cH[1],
                                      Al[i][0], Al[i][1], Al[i][2], Al[i][3],
                                      Bh[jp][2 * h], Bh[jp][2 * h + 1]);
                        }
            }
        }
        __syncthreads();   // compute done before this buffer is reloaded
        if (c + 2 < NC) load_stage(c & 1, c + 2);
    }

    // ---- epilogue: D = acc(f32) + unpack(accH f16) ----
    #pragma unroll
    for (int i = 0; i < 4; i++) {
        const int row0 = rowBase + mW + i * 16 + (lane >> 2);
        #pragma unroll
        for (int j = 0; j < 4; j++) {
            const int col = colBase + nW + j * 8 + (lane & 3) * 2;
            float2 c0 = __half22float2(*(__half2*)&accH[i][j][0]);
            float2 c1 = __half22float2(*(__half2*)&accH[i][j][1]);
            float v00 = acc[i][j][0] + c0.x;
            float v01 = acc[i][j][1] + c0.y;
            float v10 = acc[i][j][2] + c1.x;
            float v11 = acc[i][j][3] + c1.y;
            if (MODE == 0) {
                float* d0 = Df + (size_t)row0 * N + col;
                float* d1 = Df + (size_t)(row0 + 8) * N + col;
                d0[0] = v00; d0[1] = v01;
                d1[0] = v10; d1[1] = v11;
            } else {
                float vs[2][2] = {{v00, v01}, {v10, v11}};
                #pragma unroll
                for (int h = 0; h < 2; h++) {
                    const size_t off = (size_t)(row0 + 8 * h) * N + col;
                    __half2 hv = __floats2half2_rn(vs[h][0], vs[h][1]);
                    float2 hf = __half22float2(hv);
                    __half2 lv = __floats2half2_rn(vs[h][0] - hf.x, vs[h][1] - hf.y);
                    *(__half2*)(Dhi + off) = hv;
                    *(__half2*)(Dlo + off) = lv;
                }
            }
        }
    }
}

// =========================================================================
// Per-image gram (symmetric): 666 upper-triangle dots per 128-d chunk.
// grid (64, 8), atomicAdd both triangles (G pre-zeroed).
// =========================================================================
__global__ __launch_bounds__(256)
void gram_kernel(const float* __restrict__ img, float* __restrict__ G) {
    __shared__ float ch[NS][132];
    const int b = blockIdx.x;
    const int d0 = blockIdx.y * 128;
    const float* base = img + (size_t)b * NS * DIM + d0;

    for (int idx = threadIdx.x; idx < NS * 32; idx += 256) {
        int s = idx >> 5, c4 = idx & 31;
        *(float4*)&ch[s][c4 * 4] = *(const float4*)(base + (size_t)s * DIM + c4 * 4);
    }
    __syncthreads();

    for (int p = threadIdx.x; p < (NS * (NS + 1)) / 2; p += 256) {
        int idx = p, s = 0, rem = NS;
        while (idx >= rem) { idx -= rem; rem--; s++; }
        int s2 = s + idx;
        const float4* r1 = (const float4*)&ch[s][0];
        const float4* r2 = (const float4*)&ch[s2][0];
        float a = 0.f;
        #pragma unroll
        for (int q = 0; q < 32; q++) {
            float4 x = r1[q], y = r2[q];
            a += x.x * y.x + x.y * y.y + x.z * y.z + x.w * y.w;
        }
        atomicAdd(&G[(size_t)b * NS * NS + s * NS + s2], a);
        if (s2 != s) atomicAdd(&G[(size_t)b * NS * NS + s2 * NS + s], a);
    }
}

// =========================================================================
// Caption word norms
// =========================================================================
__global__ __launch_bounds__(1024)
void capnorm_kernel(const float* __restrict__ cap, float* __restrict__ w1) {
    const int i = blockIdx.x, warp = threadIdx.x >> 5, lane = threadIdx.x & 31;
    const float4* row = (const float4*)(cap + (size_t)(i * NL + warp) * DIM);
    float s = 0.f;
    #pragma unroll 8
    for (int q = lane; q < DIM / 4; q += 32) {
        float4 v = row[q];
        s += v.x * v.x + v.y * v.y + v.z * v.z + v.w * v.w;
    }
    #pragma unroll
    for (int o = 16; o; o >>= 1) s += __shfl_down_sync(0xffffffffu, s, o);
    if (lane == 0) w1[i * NL + warp] = sqrtf(s);
}

// =========================================================================
// Per-(image b, caption i) finishing kernel. grid (i=64, b=64), 128 threads.
// =========================================================================
__global__ __launch_bounds__(128)
void pair_kernel(const float* __restrict__ Aarr, const float* __restrict__ Carr,
                 const float* __restrict__ G, const float* __restrict__ w1,
                 const int* __restrict__ cap_lens, float* __restrict__ out) {
    const int i = blockIdx.x;   // caption
    const int b = blockIdx.y;   // image
    const int tid = threadIdx.x;
    const int len = cap_lens[i];

    __shared__ float T[NS][33];
    __shared__ float Cs[NS][33];
    __shared__ float Gs[NS][37];
    __shared__ float Ws[NL][37];
    __shared__ float ninv[NS];
    __shared__ float w12s[NL], w2s[NL];

    const float* Abase = Aarr + (size_t)(b * NS) * CROWS + i * NL;
    const float* Cbase = Carr + (size_t)(b * NS) * CROWS + i * NL;

    for (int idx = tid; idx < NS * NL; idx += 128) {
        int s = idx >> 5, l = idx & 31;
        float v = Abase[(size_t)s * CROWS + l];
        v = (v > 0.f) ? v : 0.1f * v;       // LeakyReLU(0.1)
        if (l >= len) v = 0.f;              // word mask
        T[s][l]  = v;
        Cs[s][l] = Cbase[(size_t)s * CROWS + l];
    }
    for (int idx = tid; idx < NS * NS; idx += 128)
        Gs[idx / NS][idx % NS] = G[(size_t)b * NS * NS + idx];
    __syncthreads();

    if (tid < NS) {
        float sum = 0.f;
        #pragma unroll
        for (int l = 0; l < NL; l++) { float v = T[tid][l]; sum += v * v; }
        ninv[tid] = 9.0f / (sqrtf(sum) + 1e-8f);
    }
    __syncthreads();

    if (tid < NL) {
        const int l = tid;
        float m = -1e30f;
        #pragma unroll
        for (int s = 0; s < NS; s++) m = fmaxf(m, T[s][l] * ninv[s]);
        float sum = 0.f;
        #pragma unroll
        for (int s = 0; s < NS; s++) {
            float e = __expf(T[s][l] * ninv[s] - m);
            Ws[l][s] = e; sum += e;
        }
        float rr = 1.0f / sum;
        #pragma unroll
        for (int s = 0; s < NS; s++) Ws[l][s] *= rr;
    }
    __syncthreads();

    const int warp = tid >> 5, lane = tid & 31;
    for (int l = warp; l < NL; l += 4) {
        float w12 = 0.f, w2 = 0.f;
        for (int s = lane; s < NS; s += 32) {
            float w = Ws[l][s];
            w12 += w * Cs[s][l];
            float v = 0.f;
            #pragma unroll
            for (int s2 = 0; s2 < NS; s2++) v += Gs[s][s2] * Ws[l][s2];
            w2 += w * v;
        }
        #pragma unroll
        for (int o = 16; o; o >>= 1) {
            w12 += __shfl_down_sync(0xffffffffu, w12, o);
            w2  += __shfl_down_sync(0xffffffffu, w2, o);
        }
        if (lane == 0) { w12s[l] = w12; w2s[l] = w2; }
    }
    __syncthreads();

    if (warp == 0) {
        const int l = lane;
        float z;
        if (l < len) {
            float denom = fmaxf(w1[i * NL + l] * sqrtf(fmaxf(w2s[l], 0.f)), 1e-8f);
            z = 6.0f * (w12s[l] / denom);
        } else {
            z = -1e30f;
        }
        float m = z;
        #pragma unroll
        for (int o = 16; o; o >>= 1) m = fmaxf(m, __shfl_xor_sync(0xffffffffu, m, o));
        float e = expf(z - m);
        #pragma unroll
        for (int o = 16; o; o >>= 1) e += __shfl_xor_sync(0xffffffffu, e, o);
        if (lane == 0) out[b * NB + i] = (m + logf(e)) / 6.0f;
    }
}

// =========================================================================
extern "C" void kernel_launch(void* const* d_in, const int* in_sizes, int n_in,
                              void* d_out, int out_size) {
    const float* images   = (const float*)d_in[0];   // (64,36,1024)
    const float* captions = (const float*)d_in[1];   // (64,32,1024)
    const int*   cap_lens = (const int*)d_in[2];     // (64,)
    const float* W_g      = (const float*)d_in[3];   // (1024,1024)
    float* out = (float*)d_out;                      // (64,64)

    static float *pA = nullptr, *pC = nullptr, *pG = nullptr, *pw1 = nullptr;
    static __half *pIhi, *pIlo, *pPhi, *pPlo, *pWhi, *pWlo, *pEhi, *pElo;
    static cudaStream_t s1;
    static cudaEvent_t e0, e1;
    static bool init = false;
    if (!init) {
        cudaGetSymbolAddress((void**)&pA,  g_A);
        cudaGetSymbolAddress((void**)&pC,  g_C);
        cudaGetSymbolAddress((void**)&pG,  g_G);
        cudaGetSymbolAddress((void**)&pw1, g_w1);
        cudaGetSymbolAddress((void**)&pIhi, g_Ihi);
        cudaGetSymbolAddress((void**)&pIlo, g_Ilo);
        cudaGetSymbolAddress((void**)&pPhi, g_Phi);
        cudaGetSymbolAddress((void**)&pPlo, g_Plo);
        cudaGetSymbolAddress((void**)&pWhi, g_Whi);
        cudaGetSymbolAddress((void**)&pWlo, g_Wlo);
        cudaGetSymbolAddress((void**)&pEhi, g_Ehi);
        cudaGetSymbolAddress((void**)&pElo, g_Elo);
        cudaFuncSetAttribute((const void*)gemm_tc_kernel<0,3>, cudaFuncAttributeMaxDynamicSharedMemorySize, GEMM_SMEM);
        cudaFuncSetAttribute((const void*)gemm_tc_kernel<0,2>, cudaFuncAttributeMaxDynamicSharedMemorySize, GEMM_SMEM);
        cudaFuncSetAttribute((const void*)gemm_tc_kernel<1,2>, cudaFuncAttributeMaxDynamicSharedMemorySize, GEMM_SMEM);
        cudaStreamCreateWithFlags(&s1, cudaStreamNonBlocking);
        cudaEventCreateWithFlags(&e0, cudaEventDisableTiming);
        cudaEventCreateWithFlags(&e1, cudaEventDisableTiming);
        init = true;
    }

    // 0) split inputs to fp16 hi/lo (stream 0)
    split_kernel<<<(MROWS * DIM / 4 + 255) / 256, 256>>>((const float4*)images, (__half2*)pIhi, (__half2*)pIlo, MROWS * DIM / 4);
    split_kernel<<<(CROWS * DIM / 4 + 255) / 256, 256>>>((const float4*)captions, (__half2*)pPhi, (__half2*)pPlo, CROWS * DIM / 4);
    split_kernel<<<(DIM * DIM / 4 + 255) / 256, 256>>>((const float4*)W_g, (__half2*)pWhi, (__half2*)pWlo, DIM * DIM / 4);

    // fork: branch s1 handles gram, capnorm, gemm3 (all independent of E/A)
    cudaEventRecord(e0, 0);
    cudaStreamWaitEvent(s1, e0, 0);

    // ---- branch s1 ----
    cudaMemsetAsync(pG, 0, (size_t)NB * NS * NS * sizeof(float), s1);
    gram_kernel<<<dim3(NB, 8), 256, 0, s1>>>(images, pG);
    capnorm_kernel<<<NB, 1024, 0, s1>>>(captions, pw1);
    // 3) C = images @ captions^T (2304 x 2048) fp32, 3 products (direct path)
    gemm_tc_kernel<0,3><<<dim3(CROWS / 128, MROWS / 128), 256, GEMM_SMEM, s1>>>(
        pIhi, pIlo, pPhi, pPlo, pC, nullptr, nullptr, MROWS, CROWS, DIM);
    cudaEventRecord(e1, s1);

    // ---- branch stream 0 ----
    // 1) E = captions @ W_g^T -> split fp16 out (2048 x 1024), 2 products
    gemm_tc_kernel<1,2><<<dim3(DIM / 128, CROWS / 128), 256, GEMM_SMEM>>>(
        pPhi, pPlo, pWhi, pWlo, nullptr, pEhi, pElo, CROWS, DIM, DIM);
    // 2) A = images @ E^T (2304 x 2048) fp32, 2 products (softmax path)
    gemm_tc_kernel<0,2><<<dim3(CROWS / 128, MROWS / 128), 256, GEMM_SMEM>>>(
        pIhi, pIlo, pEhi, pElo, pA, nullptr, nullptr, MROWS, CROWS, DIM);

    // join and finish
    cudaStreamWaitEvent(0, e1, 0);
    pair_kernel<<<dim3(NB, NB), 128>>>(pA, pC, pG, pw1, cap_lens, out);
}

// round 17
// speedup vs baseline: 1.3586x; 1.1627x over previous
#include <cuda_runtime.h>
#include <cuda_fp16.h>
#include <math.h>
#include <stdint.h>

// Problem constants
#define DIM   1024
#define NB    64      // n_image == n_caption
#define NS    36      // regions
#define NL    32      // max caption length
#define MROWS (NB*NS)     // 2304 image rows
#define CROWS (NB*NL)     // 2048 caption rows

// ---------------- device scratch (no allocations allowed) ----------------
__device__ float  g_A[MROWS * CROWS];     // attn logits img . E    (2304x2048)
__device__ float  g_C[MROWS * CROWS];     // img . cap dots         (2304x2048)
__device__ float  g_G[NB * NS * NS];      // per-image gram         (64x36x36)
__device__ float  g_w1[CROWS];            // caption word norms     (2048)
__device__ __half g_Ihi[MROWS * DIM], g_Ilo[MROWS * DIM];   // images split
__device__ __half g_Phi[CROWS * DIM], g_Plo[CROWS * DIM];   // captions split
__device__ __half g_Whi[DIM * DIM],   g_Wlo[DIM * DIM];     // W_g split
__device__ __half g_Ehi[CROWS * DIM], g_Elo[CROWS * DIM];   // energy split

__device__ __forceinline__ uint32_t smem_u32(const void* p) {
    uint32_t a;
    asm("{ .reg .u64 t; cvta.to.shared.u64 t, %1; cvt.u32.u64 %0, t; }" : "=r"(a) : "l"(p));
    return a;
}

#define LDSM_X4(r0, r1, r2, r3, addr) \
    asm volatile("ldmatrix.sync.aligned.m8n8.x4.shared.b16 {%0,%1,%2,%3}, [%4];" \
                 : "=r"(r0), "=r"(r1), "=r"(r2), "=r"(r3) : "r"(addr))

// fp32-accumulator MMA — dominant hi*hi product
#define MMA16816(c0, c1, c2, c3, a0, a1, a2, a3, b0, b1) \
    asm volatile("mma.sync.aligned.m16n8k16.row.col.f32.f16.f16.f32 " \
                 "{%0,%1,%2,%3}, {%4,%5,%6,%7}, {%8,%9}, {%0,%1,%2,%3};" \
                 : "+f"(c0), "+f"(c1), "+f"(c2), "+f"(c3) \
                 : "r"(a0), "r"(a1), "r"(a2), "r"(a3), "r"(b0), "r"(b1))

// fp16-accumulator MMA — small hi*lo correction
#define MMA16816H(c0, c1, a0, a1, a2, a3, b0, b1) \
    asm volatile("mma.sync.aligned.m16n8k16.row.col.f16.f16.f16.f16 " \
                 "{%0,%1}, {%2,%3,%4,%5}, {%6,%7}, {%0,%1};" \
                 : "+r"(c0), "+r"(c1) \
                 : "r"(a0), "r"(a1), "r"(a2), "r"(a3), "r"(b0), "r"(b1))

#define CP_ASYNC16(dst, src) \
    asm volatile("cp.async.cg.shared.global [%0], [%1], 16;" :: "r"(dst), "l"(src))
#define CP_COMMIT() asm volatile("cp.async.commit_group;")
#define CP_WAIT1()  asm volatile("cp.async.wait_group 1;")
#define CP_WAIT0()  asm volatile("cp.async.wait_group 0;")

// =========================================================================
// Fused fp32 -> (hi, lo) fp16 split for images, captions, W_g. One launch.
// =========================================================================
#define NI4 (MROWS * DIM / 4)   // 589824
#define NP4 (CROWS * DIM / 4)   // 524288
#define NW4 (DIM * DIM / 4)     // 262144
__global__ __launch_bounds__(256)
void split_all_kernel(const float4* __restrict__ I, const float4* __restrict__ P,
                      const float4* __restrict__ W,
                      __half2* __restrict__ Ihi, __half2* __restrict__ Ilo,
                      __half2* __restrict__ Phi, __half2* __restrict__ Plo,
                      __half2* __restrict__ Whi, __half2* __restrict__ Wlo) {
    int idx = blockIdx.x * 256 + threadIdx.x;
    const float4* src; __half2 *hi, *lo; int off;
    if (idx < NI4)                { src = I; hi = Ihi; lo = Ilo; off = idx; }
    else if (idx < NI4 + NP4)     { src = P; hi = Phi; lo = Plo; off = idx - NI4; }
    else                          { src = W; hi = Whi; lo = Wlo; off = idx - NI4 - NP4; }
    float4 v = src[off];
    __half2 h0 = __floats2half2_rn(v.x, v.y);
    __half2 h1 = __floats2half2_rn(v.z, v.w);
    float2 f0 = __half22float2(h0);
    float2 f1 = __half22float2(h1);
    hi[2 * off]     = h0;
    hi[2 * off + 1] = h1;
    lo[2 * off]     = __floats2half2_rn(v.x - f0.x, v.y - f0.y);
    lo[2 * off + 1] = __floats2half2_rn(v.z - f1.x, v.w - f1.y);
}

// =========================================================================
// Split-fp16 tensor-core NT GEMM, cp.async double-buffered.
// D = Ahi*Bhi (f32 acc) + Ahi*Blo (f16 acc)   [lo*hi dropped, ~calibrated 1e-5]
// CTA tile 128x128, 8 warps, warp tile 64x32, K-chunk 64, 2-stage smem.
// MODE 0: write fp32 D.  MODE 1: write split fp16 (Dhi, Dlo).
// =========================================================================
#define SROWB 144                  // smem row stride bytes (72 halves)
#define TILE  (128 * SROWB)        // 18432 B per operand tile
#define STAGE (4 * TILE)           // Ah, Al, Bh, Bl
#define GEMM_SMEM (2 * STAGE)      // 147456 B

template<int MODE>
__global__ __launch_bounds__(256, 1)
void gemm_tc_kernel(const __half* __restrict__ Ahi, const __half* __restrict__ Alo,
                    const __half* __restrict__ Bhi, const __half* __restrict__ Blo,
                    float* __restrict__ Df, __half* __restrict__ Dhi, __half* __restrict__ Dlo,
                    int M, int N, int K) {
    extern __shared__ char smem[];
    const uint32_t sbase = smem_u32(smem);

    const int tid = threadIdx.x;
    const int wid = tid >> 5, lane = tid & 31;
    const int rowBase = blockIdx.y * 128;
    const int colBase = blockIdx.x * 128;

    // warp tiling: 2 (m) x 4 (n) warps; warp tile 64x32
    const int mW = (wid >> 2) * 64;
    const int nW = (wid & 3) * 32;

    float acc[4][4][4];          // hi*hi, fp32
    uint32_t accH[4][4][2];      // hi*lo correction, fp16x2 packed
    #pragma unroll
    for (int i = 0; i < 4; i++)
        #pragma unroll
        for (int j = 0; j < 4; j++) {
            #pragma unroll
            for (int q = 0; q < 4; q++) acc[i][j][q] = 0.f;
            accH[i][j][0] = 0u; accH[i][j][1] = 0u;
        }

    // ldmatrix source coordinates (fixed per thread)
    const int aRow = mW + (lane & 15);
    const int aColOff = (lane >> 4) * 8;
    const int bRow = nW + (lane & 7) + ((lane >> 4) << 3);
    const int bColOff = ((lane >> 3) & 1) * 8;

    const __half* srcs[4] = {Ahi, Alo, Bhi, Blo};
    const int NC = K >> 6;   // K/64

    // loader: stage s <- K-chunk c; per array: 4x 16B per thread
    auto load_stage = [&](int s, int c) {
        const uint32_t dstStage = sbase + s * STAGE;
        #pragma unroll
        for (int a = 0; a < 4; a++) {
            const int tileRow = (a < 2) ? rowBase : colBase;
            const __half* src = srcs[a];
            #pragma unroll
            for (int q = 0; q < 4; q++) {
                int id = tid + 256 * q;          // 0..1023
                int row = id >> 3, cc = id & 7;
                const __half* sp = src + (size_t)(tileRow + row) * K + c * 64 + cc * 8;
                uint32_t dp = dstStage + a * TILE + row * SROWB + cc * 16;
                CP_ASYNC16(dp, sp);
            }
        }
        CP_COMMIT();
    };

    load_stage(0, 0);
    if (NC > 1) load_stage(1, 1);

    for (int c = 0; c < NC; c++) {
        if (c + 1 < NC) { CP_WAIT1(); } else { CP_WAIT0(); }
        __syncthreads();

        const uint32_t st = sbase + (c & 1) * STAGE;

        #pragma unroll
        for (int kk = 0; kk < 64; kk += 16) {
            uint32_t Ah[4][4], Bh[2][4], Bl[2][4];
            #pragma unroll
            for (int i = 0; i < 4; i++) {
                uint32_t ro = (aRow + i * 16) * SROWB + (kk + aColOff) * 2;
                LDSM_X4(Ah[i][0], Ah[i][1], Ah[i][2], Ah[i][3], st + ro);
            }
            #pragma unroll
            for (int jp = 0; jp < 2; jp++) {
                uint32_t ro = (bRow + jp * 16) * SROWB + (kk + bColOff) * 2;
                LDSM_X4(Bh[jp][0], Bh[jp][1], Bh[jp][2], Bh[jp][3], st + 2 * TILE + ro);
                LDSM_X4(Bl[jp][0], Bl[jp][1], Bl[jp][2], Bl[jp][3], st + 3 * TILE + ro);
            }
            // Pass 1: hi*hi (fp32 accum)
            #pragma unroll
            for (int i = 0; i < 4; i++)
                #pragma unroll
                for (int jp = 0; jp < 2; jp++)
                    #pragma unroll
                    for (int h = 0; h < 2; h++) {
                        float* cc2 = acc[i][jp * 2 + h];
                        MMA16816(cc2[0], cc2[1], cc2[2], cc2[3],
                                 Ah[i][0], Ah[i][1], Ah[i][2], Ah[i][3],
                                 Bh[jp][2 * h], Bh[jp][2 * h + 1]);
                    }
            // Pass 2: hi*lo (fp16 accum)
            #pragma unroll
            for (int i = 0; i < 4; i++)
                #pragma unroll
                for (int jp = 0; jp < 2; jp++)
                    #pragma unroll
                    for (int h = 0; h < 2; h++) {
                        uint32_t* cH = accH[i][jp * 2 + h];
                        MMA16816H(cH[0], cH[1],
                                  Ah[i][0], Ah[i][1], Ah[i][2], Ah[i][3],
                                  Bl[jp][2 * h], Bl[jp][2 * h + 1]);
                    }
        }
        __syncthreads();   // compute done before this buffer is reloaded
        if (c + 2 < NC) load_stage(c & 1, c + 2);
    }

    // ---- epilogue: D = acc(f32) + unpack(accH f16) ----
    #pragma unroll
    for (int i = 0; i < 4; i++) {
        const int row0 = rowBase + mW + i * 16 + (lane >> 2);
        #pragma unroll
        for (int j = 0; j < 4; j++) {
            const int col = colBase + nW + j * 8 + (lane & 3) * 2;
            float2 c0 = __half22float2(*(__half2*)&accH[i][j][0]);
            float2 c1 = __half22float2(*(__half2*)&accH[i][j][1]);
            float v00 = acc[i][j][0] + c0.x;
            float v01 = acc[i][j][1] + c0.y;
            float v10 = acc[i][j][2] + c1.x;
            float v11 = acc[i][j][3] + c1.y;
            if (MODE == 0) {
                float* d0 = Df + (size_t)row0 * N + col;
                float* d1 = Df + (size_t)(row0 + 8) * N + col;
                d0[0] = v00; d0[1] = v01;
                d1[0] = v10; d1[1] = v11;
            } else {
                float vs[2][2] = {{v00, v01}, {v10, v11}};
                #pragma unroll
                for (int h = 0; h < 2; h++) {
                    const size_t off = (size_t)(row0 + 8 * h) * N + col;
                    __half2 hv = __floats2half2_rn(vs[h][0], vs[h][1]);
                    float2 hf = __half22float2(hv);
                    __half2 lv = __floats2half2_rn(vs[h][0] - hf.x, vs[h][1] - hf.y);
                    *(__half2*)(Dhi + off) = hv;
                    *(__half2*)(Dlo + off) = lv;
                }
            }
        }
    }
}

// =========================================================================
// Per-image gram (symmetric): 666 upper-triangle dots per 128-d chunk.
// grid (64, 8), atomicAdd both triangles (G pre-zeroed).
// =========================================================================
__global__ __launch_bounds__(256)
void gram_kernel(const float* __restrict__ img, float* __restrict__ G) {
    __shared__ float ch[NS][132];
    const int b = blockIdx.x;
    const int d0 = blockIdx.y * 128;
    const float* base = img + (size_t)b * NS * DIM + d0;

    for (int idx = threadIdx.x; idx < NS * 32; idx += 256) {
        int s = idx >> 5, c4 = idx & 31;
        *(float4*)&ch[s][c4 * 4] = *(const float4*)(base + (size_t)s * DIM + c4 * 4);
    }
    __syncthreads();

    for (int p = threadIdx.x; p < (NS * (NS + 1)) / 2; p += 256) {
        int idx = p, s = 0, rem = NS;
        while (idx >= rem) { idx -= rem; rem--; s++; }
        int s2 = s + idx;
        const float4* r1 = (const float4*)&ch[s][0];
        const float4* r2 = (const float4*)&ch[s2][0];
        float a = 0.f;
        #pragma unroll
        for (int q = 0; q < 32; q++) {
            float4 x = r1[q], y = r2[q];
            a += x.x * y.x + x.y * y.y + x.z * y.z + x.w * y.w;
        }
        atomicAdd(&G[(size_t)b * NS * NS + s * NS + s2], a);
        if (s2 != s) atomicAdd(&G[(size_t)b * NS * NS + s2 * NS + s], a);
    }
}

// =========================================================================
// Caption word norms
// =========================================================================
__global__ __launch_bounds__(1024)
void capnorm_kernel(const float* __restrict__ cap, float* __restrict__ w1) {
    const int i = blockIdx.x, warp = threadIdx.x >> 5, lane = threadIdx.x & 31;
    const float4* row = (const float4*)(cap + (size_t)(i * NL + warp) * DIM);
    float s = 0.f;
    #pragma unroll 8
    for (int q = lane; q < DIM / 4; q += 32) {
        float4 v = row[q];
        s += v.x * v.x + v.y * v.y + v.z * v.z + v.w * v.w;
    }
    #pragma unroll
    for (int o = 16; o; o >>= 1) s += __shfl_down_sync(0xffffffffu, s, o);
    if (lane == 0) w1[i * NL + warp] = sqrtf(s);
}

// =========================================================================
// Per-(image b, caption i) finishing kernel. grid (i=64, b=64), 128 threads.
// Restructured: cooperative u = G·w with float4 register blocking (4 l/thread)
// to cut LDS instruction count ~3.4x.
// =========================================================================
__global__ __launch_bounds__(128)
void pair_kernel(const float* __restrict__ Aarr, const float* __restrict__ Carr,
                 const float* __restrict__ G, const float* __restrict__ w1,
                 const int* __restrict__ cap_lens, float* __restrict__ out) {
    const int i = blockIdx.x;   // caption
    const int b = blockIdx.y;   // image
    const int tid = threadIdx.x;
    const int len = cap_lens[i];

    __shared__ float T[NS][33];     // masked leaky attn [s][l]
    __shared__ float Cs[NS][33];    // C tile [s][l]
    __shared__ float Gs[NS][37];    // gram [s][s2] (stride 37: conflict-free)
    __shared__ float WsT[NS][36];   // softmax weights [s][l] (stride 144B: f4-aligned)
    __shared__ float Us[NL][37];    // u[l][s] = (G w_l)[s]
    __shared__ float ninv[NS];
    __shared__ float w12s[NL], w2s[NL];

    const float* Abase = Aarr + (size_t)(b * NS) * CROWS + i * NL;
    const float* Cbase = Carr + (size_t)(b * NS) * CROWS + i * NL;

    for (int idx = tid; idx < NS * NL; idx += 128) {
        int s = idx >> 5, l = idx & 31;
        float v = Abase[(size_t)s * CROWS + l];
        v = (v > 0.f) ? v : 0.1f * v;       // LeakyReLU(0.1)
        if (l >= len) v = 0.f;              // word mask
        T[s][l]  = v;
        Cs[s][l] = Cbase[(size_t)s * CROWS + l];
    }
    for (int idx = tid; idx < NS * NS; idx += 128)
        Gs[idx / NS][idx % NS] = G[(size_t)b * NS * NS + idx];
    __syncthreads();

    // per-region l2 norm over words; fold in SMOOTH=9
    if (tid < NS) {
        float sum = 0.f;
        #pragma unroll
        for (int l = 0; l < NL; l++) { float v = T[tid][l]; sum += v * v; }
        ninv[tid] = 9.0f / (sqrtf(sum) + 1e-8f);
    }
    __syncthreads();

    // softmax over regions per word l; store transposed WsT[s][l]
    if (tid < NL) {
        const int l = tid;
        float m = -1e30f;
        #pragma unroll
        for (int s = 0; s < NS; s++) m = fmaxf(m, T[s][l] * ninv[s]);
        float sum = 0.f;
        float e[NS];
        #pragma unroll
        for (int s = 0; s < NS; s++) {
            e[s] = __expf(T[s][l] * ninv[s] - m);
            sum += e[s];
        }
        float rr = 1.0f / sum;
        #pragma unroll
        for (int s = 0; s < NS; s++) WsT[s][l] = e[s] * rr;
    }
    __syncthreads();

    // Phase 1: u[l][s] = sum_s2 Gs[s][s2] * w[l][s2], 4 l's per task via float4
    for (int task = tid; task < 8 * NS; task += 128) {
        const int lq = task / NS;      // l-group 0..7 (l = 4*lq .. 4*lq+3)
        const int s  = task % NS;
        float4 v = make_float4(0.f, 0.f, 0.f, 0.f);
        #pragma unroll
        for (int s2 = 0; s2 < NS; s2++) {
            float g = Gs[s][s2];
            float4 w = *(const float4*)&WsT[s2][lq * 4];
            v.x += g * w.x; v.y += g * w.y; v.z += g * w.z; v.w += g * w.w;
        }
        Us[lq * 4 + 0][s] = v.x;
        Us[lq * 4 + 1][s] = v.y;
        Us[lq * 4 + 2][s] = v.z;
        Us[lq * 4 + 3][s] = v.w;
    }
    __syncthreads();

    // Phase 2: w12[l] = sum_s w*Cs;  w2[l] = sum_s w*u
    const int warp = tid >> 5, lane = tid & 31;
    for (int l = warp; l < NL; l += 4) {
        float w12 = 0.f, w2 = 0.f;
        for (int s = lane; s < NS; s += 32) {
            float w = WsT[s][l];
            w12 += w * Cs[s][l];
            w2  += w * Us[l][s];
        }
        #pragma unroll
        for (int o = 16; o; o >>= 1) {
            w12 += __shfl_down_sync(0xffffffffu, w12, o);
            w2  += __shfl_down_sync(0xffffffffu, w2, o);
        }
        if (lane == 0) { w12s[l] = w12; w2s[l] = w2; }
    }
    __syncthreads();

    // cosine + LogSumExp over valid words
    if (warp == 0) {
        const int l = lane;
        float z;
        if (l < len) {
            float denom = fmaxf(w1[i * NL + l] * sqrtf(fmaxf(w2s[l], 0.f)), 1e-8f);
            z = 6.0f * (w12s[l] / denom);
        } else {
            z = -1e30f;
        }
        float m = z;
        #pragma unroll
        for (int o = 16; o; o >>= 1) m = fmaxf(m, __shfl_xor_sync(0xffffffffu, m, o));
        float e = expf(z - m);
        #pragma unroll
        for (int o = 16; o; o >>= 1) e += __shfl_xor_sync(0xffffffffu, e, o);
        if (lane == 0) out[b * NB + i] = (m + logf(e)) / 6.0f;
    }
}

// =========================================================================
extern "C" void kernel_launch(void* const* d_in, const int* in_sizes, int n_in,
                              void* d_out, int out_size) {
    const float* images   = (const float*)d_in[0];   // (64,36,1024)
    const float* captions = (const float*)d_in[1];   // (64,32,1024)
    const int*   cap_lens = (const int*)d_in[2];     // (64,)
    const float* W_g      = (const float*)d_in[3];   // (1024,1024)
    float* out = (float*)d_out;                      // (64,64)

    static float *pA = nullptr, *pC = nullptr, *pG = nullptr, *pw1 = nullptr;
    static __half *pIhi, *pIlo, *pPhi, *pPlo, *pWhi, *pWlo, *pEhi, *pElo;
    static cudaStream_t s1;
    static cudaEvent_t e0, e1;
    static bool init = false;
    if (!init) {
        cudaGetSymbolAddress((void**)&pA,  g_A);
        cudaGetSymbolAddress((void**)&pC,  g_C);
        cudaGetSymbolAddress((void**)&pG,  g_G);
        cudaGetSymbolAddress((void**)&pw1, g_w1);
        cudaGetSymbolAddress((void**)&pIhi, g_Ihi);
        cudaGetSymbolAddress((void**)&pIlo, g_Ilo);
        cudaGetSymbolAddress((void**)&pPhi, g_Phi);
        cudaGetSymbolAddress((void**)&pPlo, g_Plo);
        cudaGetSymbolAddress((void**)&pWhi, g_Whi);
        cudaGetSymbolAddress((void**)&pWlo, g_Wlo);
        cudaGetSymbolAddress((void**)&pEhi, g_Ehi);
        cudaGetSymbolAddress((void**)&pElo, g_Elo);
        cudaFuncSetAttribute((const void*)gemm_tc_kernel<0>, cudaFuncAttributeMaxDynamicSharedMemorySize, GEMM_SMEM);
        cudaFuncSetAttribute((const void*)gemm_tc_kernel<1>, cudaFuncAttributeMaxDynamicSharedMemorySize, GEMM_SMEM);
        cudaStreamCreateWithFlags(&s1, cudaStreamNonBlocking);
        cudaEventCreateWithFlags(&e0, cudaEventDisableTiming);
        cudaEventCreateWithFlags(&e1, cudaEventDisableTiming);
        init = true;
    }

    // 0) split all inputs to fp16 hi/lo (single launch, 5376 blocks)
    split_all_kernel<<<(NI4 + NP4 + NW4) / 256, 256>>>(
        (const float4*)images, (const float4*)captions, (const float4*)W_g,
        (__half2*)pIhi, (__half2*)pIlo, (__half2*)pPhi, (__half2*)pPlo,
        (__half2*)pWhi, (__half2*)pWlo);

    // fork: branch s1 handles gram, capnorm, gemm3 (independent of E/A)
    cudaEventRecord(e0, 0);
    cudaStreamWaitEvent(s1, e0, 0);

    // ---- branch s1 ----
    cudaMemsetAsync(pG, 0, (size_t)NB * NS * NS * sizeof(float), s1);
    gram_kernel<<<dim3(NB, 8), 256, 0, s1>>>(images, pG);
    capnorm_kernel<<<NB, 1024, 0, s1>>>(captions, pw1);
    // 3) C = images @ captions^T (2304 x 2048) fp32
    gemm_tc_kernel<0><<<dim3(CROWS / 128, MROWS / 128), 256, GEMM_SMEM, s1>>>(
        pIhi, pIlo, pPhi, pPlo, pC, nullptr, nullptr, MROWS, CROWS, DIM);
    cudaEventRecord(e1, s1);

    // ---- branch stream 0 ----
    // 1) E = captions @ W_g^T -> split fp16 out (2048 x 1024)
    gemm_tc_kernel<1><<<dim3(DIM / 128, CROWS / 128), 256, GEMM_SMEM>>>(
        pPhi, pPlo, pWhi, pWlo, nullptr, pEhi, pElo, CROWS, DIM, DIM);
    // 2) A = images @ E^T (2304 x 2048) fp32
    gemm_tc_kernel<0><<<dim3(CROWS / 128, MROWS / 128), 256, GEMM_SMEM>>>(
        pIhi, pIlo, pEhi, pElo, pA, nullptr, nullptr, MROWS, CROWS, DIM);

    // join and finish
    cudaStreamWaitEvent(0, e1, 0);
    pair_kernel<<<dim3(NB, NB), 128>>>(pA, pC, pG, pw1, cap_lens, out);
}